// round 1
// baseline (speedup 1.0000x reference)
#include <cuda_runtime.h>

// DWT_2D Haar: x (16,64,256,256) f32 -> (ll,lh,hl,hh) each (16,64,128,128),
// concatenated in d_out. Pure memory-bound butterfly.

#define BCN   1024   // 16*64
#define HDIM  256
#define WDIM  256
#define OH    128
#define OW    128

__global__ void __launch_bounds__(256)
dwt2d_haar_kernel(const float* __restrict__ x, float* __restrict__ out) {
    // Thread layout: tid = (bc << 12) | (i << 5) | g
    //   bc in [0,1024), i = output row in [0,128), g = group of 4 output cols in [0,32)
    unsigned tid = blockIdx.x * 256u + threadIdx.x;
    unsigned g  = tid & 31u;
    unsigned i  = (tid >> 5) & 127u;
    unsigned bc = tid >> 12;

    const float* base = x + (size_t)bc * (HDIM * WDIM) + (size_t)(2u * i) * WDIM + g * 8u;
    const float4* r0 = (const float4*)base;
    const float4* r1 = (const float4*)(base + WDIM);

    // 4 independent 128-bit loads (MLP=4 per thread)
    float4 r0a = r0[0];
    float4 r0b = r0[1];
    float4 r1a = r1[0];
    float4 r1b = r1[1];

    float t0[8] = {r0a.x, r0a.y, r0a.z, r0a.w, r0b.x, r0b.y, r0b.z, r0b.w};
    float t1[8] = {r1a.x, r1a.y, r1a.z, r1a.w, r1b.x, r1b.y, r1b.z, r1b.w};

    float llv[4], lhv[4], hlv[4], hhv[4];
#pragma unroll
    for (int k = 0; k < 4; ++k) {
        float a = t0[2 * k];
        float b = t0[2 * k + 1];
        float c = t1[2 * k];
        float d = t1[2 * k + 1];
        float spq = a + b;      // a+b
        float dpq = a - b;      // a-b
        float srs = c + d;      // c+d
        float drs = c - d;      // c-d
        llv[k] = 0.5f * (spq + srs);
        lhv[k] = 0.5f * (dpq + drs);
        hlv[k] = 0.5f * (spq - srs);
        hhv[k] = 0.5f * (dpq - drs);
    }

    const size_t band = (size_t)BCN * OH * OW;              // 16,777,216
    size_t obase = (size_t)bc * (OH * OW) + (size_t)i * OW + g * 4u;

    *(float4*)(out + obase)            = make_float4(llv[0], llv[1], llv[2], llv[3]);
    *(float4*)(out + band + obase)     = make_float4(lhv[0], lhv[1], lhv[2], lhv[3]);
    *(float4*)(out + 2 * band + obase) = make_float4(hlv[0], hlv[1], hlv[2], hlv[3]);
    *(float4*)(out + 3 * band + obase) = make_float4(hhv[0], hhv[1], hhv[2], hhv[3]);
}

extern "C" void kernel_launch(void* const* d_in, const int* in_sizes, int n_in,
                              void* d_out, int out_size) {
    const float* x = (const float*)d_in[0];
    float* out = (float*)d_out;
    // Total threads: 1024 * 128 * 32 = 4,194,304 -> 16384 blocks of 256
    dwt2d_haar_kernel<<<16384, 256>>>(x, out);
}